// round 2
// baseline (speedup 1.0000x reference)
#include <cuda_runtime.h>
#include <math.h>

#define B_ 8
#define T_ 2048
#define C_ 512
#define BT_ (B_*T_)

// Scratch (static device globals: allocation-free per harness rules)
__device__ float g_Q[BT_*C_];
__device__ float g_K[BT_*C_];
__device__ float g_V[BT_*C_];
__device__ float g_S[(size_t)B_*T_*T_];   // 134 MB logits scratch
__device__ float g_cmax[B_*T_];
__device__ float g_crz[B_*T_];

#define SCALE 0.044194173824159216f  // 1/sqrt(512)
#define NEG_BIG (-1e30f)

// ---------------------------------------------------------------------------
// Kernel A: fused QKV projection.  C[m,n] = sum_c X[m,c] * W[n,c] + b[n]
// NT GEMM, M=16384, N=512, K=512. 128x128x8 tiles, 256 thr, 8x8 microtile.
// blockIdx.z selects Q/K/V.
// ---------------------------------------------------------------------------
__global__ __launch_bounds__(256) void qkv_kernel(
    const float* __restrict__ X,
    const float* __restrict__ Wq, const float* __restrict__ bq,
    const float* __restrict__ Wk, const float* __restrict__ bk,
    const float* __restrict__ Wv, const float* __restrict__ bv)
{
    __shared__ float As[8][132];
    __shared__ float Bs[8][132];

    const float* W; const float* bias; float* Cout;
    if (blockIdx.z == 0)      { W = Wq; bias = bq; Cout = g_Q; }
    else if (blockIdx.z == 1) { W = Wk; bias = bk; Cout = g_K; }
    else                      { W = Wv; bias = bv; Cout = g_V; }

    const int tid = threadIdx.x;
    const int m0 = blockIdx.y * 128;
    const int n0 = blockIdx.x * 128;
    const int lm = tid >> 1;
    const int lk = (tid & 1) * 4;
    const float* Arow = X + (size_t)(m0 + lm) * C_ + lk;
    const float* Brow = W + (size_t)(n0 + lm) * C_ + lk;
    const int ty = tid >> 4, tx = tid & 15;

    float acc[8][8];
    #pragma unroll
    for (int r = 0; r < 8; r++)
        #pragma unroll
        for (int c = 0; c < 8; c++) acc[r][c] = 0.f;

    for (int k0 = 0; k0 < C_; k0 += 8) {
        float4 av  = *(const float4*)(Arow + k0);
        float4 bv4 = *(const float4*)(Brow + k0);
        __syncthreads();
        As[lk+0][lm] = av.x;  As[lk+1][lm] = av.y;
        As[lk+2][lm] = av.z;  As[lk+3][lm] = av.w;
        Bs[lk+0][lm] = bv4.x; Bs[lk+1][lm] = bv4.y;
        Bs[lk+2][lm] = bv4.z; Bs[lk+3][lm] = bv4.w;
        __syncthreads();
        #pragma unroll
        for (int kk = 0; kk < 8; kk++) {
            float a[8], bb[8];
            float4 t;
            t = *(const float4*)&As[kk][ty*4];      a[0]=t.x; a[1]=t.y; a[2]=t.z; a[3]=t.w;
            t = *(const float4*)&As[kk][ty*4+64];   a[4]=t.x; a[5]=t.y; a[6]=t.z; a[7]=t.w;
            t = *(const float4*)&Bs[kk][tx*4];      bb[0]=t.x;bb[1]=t.y;bb[2]=t.z;bb[3]=t.w;
            t = *(const float4*)&Bs[kk][tx*4+64];   bb[4]=t.x;bb[5]=t.y;bb[6]=t.z;bb[7]=t.w;
            #pragma unroll
            for (int r = 0; r < 8; r++)
                #pragma unroll
                for (int c = 0; c < 8; c++)
                    acc[r][c] += a[r] * bb[c];
        }
    }

    #pragma unroll
    for (int rh = 0; rh < 2; rh++)
        #pragma unroll
        for (int r = 0; r < 4; r++) {
            int m = m0 + ty*4 + r + rh*64;
            float* crow = Cout + (size_t)m * C_;
            #pragma unroll
            for (int ch = 0; ch < 2; ch++) {
                int n = n0 + tx*4 + ch*64;
                float4 o;
                o.x = acc[rh*4+r][ch*4+0] + bias[n+0];
                o.y = acc[rh*4+r][ch*4+1] + bias[n+1];
                o.z = acc[rh*4+r][ch*4+2] + bias[n+2];
                o.w = acc[rh*4+r][ch*4+3] + bias[n+3];
                *(float4*)(crow + n) = o;
            }
        }
}

// ---------------------------------------------------------------------------
// Kernel B: S[b,j,i] = (Q_b[j,:] . K_b[i,:]) * SCALE, masked (i>j) -> -1e30.
// Fully-masked tiles (n0 > m0+127) write constant and skip the GEMM.
// ---------------------------------------------------------------------------
__global__ __launch_bounds__(256) void logits_kernel()
{
    __shared__ float As[8][132];
    __shared__ float Bs[8][132];

    const int b  = blockIdx.z;
    const int tid = threadIdx.x;
    const int m0 = blockIdx.y * 128;   // j
    const int n0 = blockIdx.x * 128;   // i
    const int ty = tid >> 4, tx = tid & 15;
    float* Sb = g_S + (size_t)b * T_ * T_;

    if (n0 > m0 + 127) {  // entire tile masked
        const float4 neg = make_float4(NEG_BIG, NEG_BIG, NEG_BIG, NEG_BIG);
        #pragma unroll
        for (int rh = 0; rh < 2; rh++)
            #pragma unroll
            for (int r = 0; r < 4; r++) {
                int m = m0 + ty*4 + r + rh*64;
                float* srow = Sb + (size_t)m * T_;
                *(float4*)(srow + n0 + tx*4)      = neg;
                *(float4*)(srow + n0 + tx*4 + 64) = neg;
            }
        return;
    }

    const int lm = tid >> 1;
    const int lk = (tid & 1) * 4;
    const float* Arow = g_Q + (size_t)b*T_*C_ + (size_t)(m0 + lm) * C_ + lk;
    const float* Brow = g_K + (size_t)b*T_*C_ + (size_t)(n0 + lm) * C_ + lk;

    float acc[8][8];
    #pragma unroll
    for (int r = 0; r < 8; r++)
        #pragma unroll
        for (int c = 0; c < 8; c++) acc[r][c] = 0.f;

    for (int k0 = 0; k0 < C_; k0 += 8) {
        float4 av  = *(const float4*)(Arow + k0);
        float4 bv4 = *(const float4*)(Brow + k0);
        __syncthreads();
        As[lk+0][lm] = av.x;  As[lk+1][lm] = av.y;
        As[lk+2][lm] = av.z;  As[lk+3][lm] = av.w;
        Bs[lk+0][lm] = bv4.x; Bs[lk+1][lm] = bv4.y;
        Bs[lk+2][lm] = bv4.z; Bs[lk+3][lm] = bv4.w;
        __syncthreads();
        #pragma unroll
        for (int kk = 0; kk < 8; kk++) {
            float a[8], bb[8];
            float4 t;
            t = *(const float4*)&As[kk][ty*4];      a[0]=t.x; a[1]=t.y; a[2]=t.z; a[3]=t.w;
            t = *(const float4*)&As[kk][ty*4+64];   a[4]=t.x; a[5]=t.y; a[6]=t.z; a[7]=t.w;
            t = *(const float4*)&Bs[kk][tx*4];      bb[0]=t.x;bb[1]=t.y;bb[2]=t.z;bb[3]=t.w;
            t = *(const float4*)&Bs[kk][tx*4+64];   bb[4]=t.x;bb[5]=t.y;bb[6]=t.z;bb[7]=t.w;
            #pragma unroll
            for (int r = 0; r < 8; r++)
                #pragma unroll
                for (int c = 0; c < 8; c++)
                    acc[r][c] += a[r] * bb[c];
        }
    }

    #pragma unroll
    for (int rh = 0; rh < 2; rh++)
        #pragma unroll
        for (int r = 0; r < 4; r++) {
            int j = m0 + ty*4 + r + rh*64;
            float* srow = Sb + (size_t)j * T_;
            #pragma unroll
            for (int ch = 0; ch < 2; ch++) {
                int n = n0 + tx*4 + ch*64;
                float4 o;
                o.x = (n+0 > j) ? NEG_BIG : acc[rh*4+r][ch*4+0] * SCALE;
                o.y = (n+1 > j) ? NEG_BIG : acc[rh*4+r][ch*4+1] * SCALE;
                o.z = (n+2 > j) ? NEG_BIG : acc[rh*4+r][ch*4+2] * SCALE;
                o.w = (n+3 > j) ? NEG_BIG : acc[rh*4+r][ch*4+3] * SCALE;
                *(float4*)(srow + n) = o;
            }
        }
}

// ---------------------------------------------------------------------------
// Kernel C: per-column (b,i) online softmax stats over j (j >= i valid).
// Unroll-8 batched loads for MLP; short max/exp merge chain.
// ---------------------------------------------------------------------------
__global__ __launch_bounds__(256) void colstats_kernel()
{
    const int b = blockIdx.y;
    const int i = blockIdx.x * 256 + threadIdx.x;
    const int j0 = blockIdx.x * 256;           // rows below i are masked anyway
    const float* Scol = g_S + (size_t)b * T_ * T_ + i;

    float m = -INFINITY, s = 0.f;
    for (int j = j0; j < T_; j += 8) {
        float x[8];
        #pragma unroll
        for (int u = 0; u < 8; u++) x[u] = Scol[(size_t)(j + u) * T_];
        float lm = x[0];
        #pragma unroll
        for (int u = 1; u < 8; u++) lm = fmaxf(lm, x[u]);
        float nm = fmaxf(m, lm);
        float ls = 0.f;
        #pragma unroll
        for (int u = 0; u < 8; u++) ls += __expf(x[u] - nm);
        s = s * __expf(m - nm) + ls;
        m = nm;
    }
    g_cmax[b*T_ + i] = m;
    g_crz[b*T_ + i]  = 1.0f / s;
}

// ---------------------------------------------------------------------------
// Kernel D: read[b,j,v] = sum_i exp(S[j,i]-cmax[i])*crz[i] * V[i,v]
// NN GEMM, M=2048(j), N=512(v), K=2048(i), truncated at i-tiles <= j-tile max.
// Writes directly into out[b, j, 512+v] (row stride 1024).
// ---------------------------------------------------------------------------
__global__ __launch_bounds__(256) void read_kernel(float* __restrict__ out)
{
    __shared__ float As[8][132];
    __shared__ float Bs[8][132];

    const int b = blockIdx.z;
    const float* S  = g_S + (size_t)b * T_ * T_;
    const float* V  = g_V + (size_t)b * T_ * C_;
    const float* cm = g_cmax + b * T_;
    const float* cz = g_crz  + b * T_;

    const int tid = threadIdx.x;
    const int n0 = blockIdx.x * 128;   // v
    const int m0 = blockIdx.y * 128;   // j
    const int lm = tid >> 1;
    const int lk = (tid & 1) * 4;
    const int kb = tid >> 5;
    const int nb = (tid & 31) * 4;
    const int ty = tid >> 4, tx = tid & 15;

    float acc[8][8];
    #pragma unroll
    for (int r = 0; r < 8; r++)
        #pragma unroll
        for (int c = 0; c < 8; c++) acc[r][c] = 0.f;

    const int kmax = (m0 + 128 < T_) ? (m0 + 128) : T_;  // i > j contributes 0
    for (int k0 = 0; k0 < kmax; k0 += 8) {
        float4 sv = *(const float4*)(S + (size_t)(m0 + lm) * T_ + k0 + lk);
        float4 mv = *(const float4*)(cm + k0 + lk);
        float4 zv = *(const float4*)(cz + k0 + lk);
        float4 pv;
        pv.x = __expf(sv.x - mv.x) * zv.x;
        pv.y = __expf(sv.y - mv.y) * zv.y;
        pv.z = __expf(sv.z - mv.z) * zv.z;
        pv.w = __expf(sv.w - mv.w) * zv.w;
        float4 vv = *(const float4*)(V + (size_t)(k0 + kb) * C_ + n0 + nb);
        __syncthreads();
        As[lk+0][lm] = pv.x; As[lk+1][lm] = pv.y;
        As[lk+2][lm] = pv.z; As[lk+3][lm] = pv.w;
        *(float4*)&Bs[kb][nb] = vv;
        __syncthreads();
        #pragma unroll
        for (int kk = 0; kk < 8; kk++) {
            float a[8], bb[8];
            float4 t;
            t = *(const float4*)&As[kk][ty*4];      a[0]=t.x; a[1]=t.y; a[2]=t.z; a[3]=t.w;
            t = *(const float4*)&As[kk][ty*4+64];   a[4]=t.x; a[5]=t.y; a[6]=t.z; a[7]=t.w;
            t = *(const float4*)&Bs[kk][tx*4];      bb[0]=t.x;bb[1]=t.y;bb[2]=t.z;bb[3]=t.w;
            t = *(const float4*)&Bs[kk][tx*4+64];   bb[4]=t.x;bb[5]=t.y;bb[6]=t.z;bb[7]=t.w;
            #pragma unroll
            for (int r = 0; r < 8; r++)
                #pragma unroll
                for (int c = 0; c < 8; c++)
                    acc[r][c] += a[r] * bb[c];
        }
    }

    #pragma unroll
    for (int rh = 0; rh < 2; rh++)
        #pragma unroll
        for (int r = 0; r < 4; r++) {
            int m = m0 + ty*4 + r + rh*64;
            float* orow = out + (size_t)(b * T_ + m) * 1024 + 512;
            #pragma unroll
            for (int ch = 0; ch < 2; ch++) {
                int n = n0 + tx*4 + ch*64;
                *(float4*)(orow + n) = make_float4(acc[rh*4+r][ch*4+0],
                                                   acc[rh*4+r][ch*4+1],
                                                   acc[rh*4+r][ch*4+2],
                                                   acc[rh*4+r][ch*4+3]);
            }
        }
}

// ---------------------------------------------------------------------------
// Kernel E: copy input into out[..., 0:512]
// ---------------------------------------------------------------------------
__global__ __launch_bounds__(256) void copy_input_kernel(
    const float* __restrict__ X, float* __restrict__ out)
{
    const float4* in4 = (const float4*)X;
    float4* out4 = (float4*)out;
    int g = blockIdx.x * blockDim.x + threadIdx.x;   // 0 .. 16384*128-1
    int row = g >> 7;
    int c4  = g & 127;
    out4[(size_t)row * 256 + c4] = in4[g];
}

// ---------------------------------------------------------------------------
extern "C" void kernel_launch(void* const* d_in, const int* in_sizes, int n_in,
                              void* d_out, int out_size)
{
    const float* X  = (const float*)d_in[0];
    const float* Wq = (const float*)d_in[1];
    const float* bq = (const float*)d_in[2];
    const float* Wk = (const float*)d_in[3];
    const float* bk = (const float*)d_in[4];
    const float* Wv = (const float*)d_in[5];
    const float* bv = (const float*)d_in[6];
    float* out = (float*)d_out;

    qkv_kernel<<<dim3(4, 128, 3), 256>>>(X, Wq, bq, Wk, bk, Wv, bv);
    logits_kernel<<<dim3(16, 16, 8), 256>>>();
    colstats_kernel<<<dim3(8, 8), 256>>>();
    read_kernel<<<dim3(4, 16, 8), 256>>>(out);
    copy_input_kernel<<<8192, 256>>>(X, out);
}

// round 6
// speedup vs baseline: 3.9283x; 3.9283x over previous
#include <cuda_runtime.h>
#include <cuda_bf16.h>
#include <math.h>
#include <stdint.h>

#define B_ 8
#define T_ 2048
#define C_ 512
#define BT_ (B_*T_)
#define SCALE 0.044194173824159216f

// ---------------- globals ----------------
__device__ __nv_bfloat16 g_Xb[BT_*C_];
__device__ __nv_bfloat16 g_Wb[3*C_*C_];
__device__ __nv_bfloat16 g_Qb[BT_*C_];
__device__ __nv_bfloat16 g_Kb[BT_*C_];
__device__ __nv_bfloat16 g_Vtb[BT_*C_];          // [b][v][t], scaled in-place by crz
__device__ __nv_bfloat16 g_P[(size_t)B_*T_*T_];  // exp(S*scale) unnormalized; upper tiles stay 0
__device__ float g_crz[BT_];

// ---------------- helpers ----------------
__device__ __forceinline__ uint32_t smem_u32(const void* p) {
    uint32_t a;
    asm("{ .reg .u64 t; cvta.to.shared.u64 t, %1; cvt.u32.u64 %0, t; }" : "=r"(a) : "l"(p));
    return a;
}
__device__ __forceinline__ void cpa(uint32_t dst, const void* src) {
    asm volatile("cp.async.cg.shared.global [%0], [%1], 16;" :: "r"(dst), "l"(src));
}
__device__ __forceinline__ void ldsm4(uint32_t* r, uint32_t a) {
    asm volatile("ldmatrix.sync.aligned.m8n8.x4.shared.b16 {%0,%1,%2,%3}, [%4];"
        : "=r"(r[0]), "=r"(r[1]), "=r"(r[2]), "=r"(r[3]) : "r"(a));
}
__device__ __forceinline__ void ldsm2(uint32_t* r, uint32_t a) {
    asm volatile("ldmatrix.sync.aligned.m8n8.x2.shared.b16 {%0,%1}, [%2];"
        : "=r"(r[0]), "=r"(r[1]) : "r"(a));
}
__device__ __forceinline__ void mma16816(float* c, const uint32_t* a, const uint32_t* b) {
    asm volatile("mma.sync.aligned.m16n8k16.row.col.f32.bf16.bf16.f32 "
        "{%0,%1,%2,%3}, {%4,%5,%6,%7}, {%8,%9}, {%0,%1,%2,%3};"
        : "+f"(c[0]), "+f"(c[1]), "+f"(c[2]), "+f"(c[3])
        : "r"(a[0]), "r"(a[1]), "r"(a[2]), "r"(a[3]), "r"(b[0]), "r"(b[1]));
}

// smem tile: 128 rows x 32 bf16, row stride 40 elems (80B) -> conflict-free ldmatrix
#define RS 80                 // row stride bytes
#define MAT_BYTES (128*RS)    // 10240
#define BUF_BYTES (2*MAT_BYTES)

// load 128x32 bf16 tile gmem->smem via cp.async; src pre-offset (row0,k0); stride elems
__device__ __forceinline__ void ldt32(uint32_t dst, const __nv_bfloat16* src, int stride, int tid) {
    #pragma unroll
    for (int s = 0; s < 2; s++) {
        int slot = tid + s*256;
        int r = slot >> 2, c = slot & 3;
        cpa(dst + r*RS + c*16, (const char*)src + (size_t)r*stride*2 + c*16);
    }
}

// one BK=32 chunk of MMAs: warp tile 64(m)x32(n), acc[mt][nt][4]
__device__ __forceinline__ void compute_chunk(uint32_t aB, uint32_t bB, int lane,
                                              int wm, int wn, float acc[4][4][4]) {
    #pragma unroll
    for (int ks = 0; ks < 2; ks++) {
        uint32_t af[4][4], bf[4][2];
        int ar = wm + (lane & 15);
        int ak = ks*16 + ((lane >> 4) << 3);
        #pragma unroll
        for (int mt = 0; mt < 4; mt++) ldsm4(af[mt], aB + (ar + mt*16)*RS + ak*2);
        int br = wn + (lane & 7);
        int bk = ks*16 + (((lane >> 3) & 1) << 3);
        #pragma unroll
        for (int nt = 0; nt < 4; nt++) ldsm2(bf[nt], bB + (br + nt*8)*RS + bk*2);
        #pragma unroll
        for (int mt = 0; mt < 4; mt++)
            #pragma unroll
            for (int nt = 0; nt < 4; nt++)
                mma16816(acc[mt][nt], af[mt], bf[nt]);
    }
}

// generic double-buffered 128x128 GEMM; load(aDst,bDst,k) issues cp.async for chunk k
template<class F>
__device__ __forceinline__ void gemm_pipe(float acc[4][4][4], int nk, int tid,
                                          int lane, int wm, int wn, F load) {
    __shared__ __align__(16) char smbuf[2*BUF_BYTES];
    uint32_t sb = smem_u32(smbuf);
    #pragma unroll
    for (int mt = 0; mt < 4; mt++)
        #pragma unroll
        for (int nt = 0; nt < 4; nt++)
            #pragma unroll
            for (int c = 0; c < 4; c++) acc[mt][nt][c] = 0.f;

    load(sb, sb + MAT_BYTES, 0);
    asm volatile("cp.async.commit_group;" ::: "memory");
    for (int k = 0; k < nk; k++) {
        if (k + 1 < nk) {
            uint32_t nb = sb + ((k + 1) & 1) * BUF_BYTES;
            load(nb, nb + MAT_BYTES, k + 1);
            asm volatile("cp.async.commit_group;" ::: "memory");
            asm volatile("cp.async.wait_group 1;" ::: "memory");
        } else {
            asm volatile("cp.async.wait_group 0;" ::: "memory");
        }
        __syncthreads();
        uint32_t cb = sb + (k & 1) * BUF_BYTES;
        compute_chunk(cb, cb + MAT_BYTES, lane, wm, wn, acc);
        __syncthreads();
    }
}

// ---------------- fp32 -> bf16 ----------------
__global__ __launch_bounds__(256) void split_k(const float* __restrict__ src,
                                               __nv_bfloat16* __restrict__ dst, int n4) {
    int g = blockIdx.x * 256 + threadIdx.x;
    if (g >= n4) return;
    float4 v = ((const float4*)src)[g];
    __nv_bfloat162 a = __floats2bfloat162_rn(v.x, v.y);
    __nv_bfloat162 b = __floats2bfloat162_rn(v.z, v.w);
    uint2 o; o.x = *(uint32_t*)&a; o.y = *(uint32_t*)&b;
    ((uint2*)dst)[g] = o;
}

// ---------------- QKV projection ----------------
__global__ __launch_bounds__(256) void qkv_t(const float* __restrict__ bq,
                                             const float* __restrict__ bk,
                                             const float* __restrict__ bv) {
    const int tid = threadIdx.x, wid = tid >> 5, lane = tid & 31;
    const int wm = (wid >> 2) * 64, wn = (wid & 3) * 32;
    const int z = blockIdx.z, m0 = blockIdx.y * 128, n0 = blockIdx.x * 128;
    const __nv_bfloat16* A  = g_Xb + (size_t)m0 * C_;
    const __nv_bfloat16* Bm = g_Wb + (size_t)z * C_ * C_ + (size_t)n0 * C_;
    const float* bias = (z == 0) ? bq : (z == 1) ? bk : bv;

    float acc[4][4][4];
    gemm_pipe(acc, C_/32, tid, lane, wm, wn, [=](uint32_t ad, uint32_t bd, int k) {
        ldt32(ad, A  + k*32, C_, tid);
        ldt32(bd, Bm + k*32, C_, tid);
    });

    const int gid = lane >> 2, tig = lane & 3;
    #pragma unroll
    for (int mt = 0; mt < 4; mt++)
        #pragma unroll
        for (int nt = 0; nt < 4; nt++)
            #pragma unroll
            for (int h = 0; h < 2; h++) {
                int m = m0 + wm + mt*16 + gid + h*8;
                int n = n0 + wn + nt*8 + tig*2;
                float v0 = acc[mt][nt][h*2+0] + __ldg(bias + n);
                float v1 = acc[mt][nt][h*2+1] + __ldg(bias + n + 1);
                if (z < 2) {
                    __nv_bfloat16* Dst = (z == 0) ? g_Qb : g_Kb;
                    __nv_bfloat162 p = __floats2bfloat162_rn(v0, v1);
                    *(uint32_t*)(Dst + (size_t)m * C_ + n) = *(uint32_t*)&p;
                } else {
                    int bb = m >> 11, t = m & (T_ - 1);
                    g_Vtb[((size_t)bb * C_ + n)     * T_ + t] = __float2bfloat16_rn(v0);
                    g_Vtb[((size_t)bb * C_ + n + 1) * T_ + t] = __float2bfloat16_rn(v1);
                }
            }
}

// ---------------- logits -> unnormalized exp probs (bf16) ----------------
__global__ __launch_bounds__(256) void logits_t() {
    const int tid = threadIdx.x, wid = tid >> 5, lane = tid & 31;
    const int wm = (wid >> 2) * 64, wn = (wid & 3) * 32;
    const int b = blockIdx.y;
    int x = blockIdx.x;
    int jt = (int)((sqrtf(8.f*x + 1.f) - 1.f) * 0.5f);
    while ((jt + 1)*(jt + 2)/2 <= x) jt++;
    while (jt*(jt + 1)/2 > x) jt--;
    const int it = x - jt*(jt + 1)/2;
    const int m0 = jt * 128, n0 = it * 128;
    const __nv_bfloat16* Q = g_Qb + (size_t)b*T_*C_ + (size_t)m0 * C_;
    const __nv_bfloat16* K = g_Kb + (size_t)b*T_*C_ + (size_t)n0 * C_;

    float acc[4][4][4];
    gemm_pipe(acc, C_/32, tid, lane, wm, wn, [=](uint32_t ad, uint32_t bd, int k) {
        ldt32(ad, Q + k*32, C_, tid);
        ldt32(bd, K + k*32, C_, tid);
    });

    const int gid = lane >> 2, tig = lane & 3;
    __nv_bfloat16* Pb = g_P + (size_t)b*T_*T_;
    #pragma unroll
    for (int mt = 0; mt < 4; mt++)
        #pragma unroll
        for (int nt = 0; nt < 4; nt++)
            #pragma unroll
            for (int h = 0; h < 2; h++) {
                int j = m0 + wm + mt*16 + gid + h*8;
                int i = n0 + wn + nt*8 + tig*2;
                float e0 = (i+0 > j) ? 0.f : __expf(acc[mt][nt][h*2+0] * SCALE);
                float e1 = (i+1 > j) ? 0.f : __expf(acc[mt][nt][h*2+1] * SCALE);
                __nv_bfloat162 p = __floats2bfloat162_rn(e0, e1);
                *(uint32_t*)(Pb + (size_t)j * T_ + i) = *(uint32_t*)&p;
            }
}

// ---------------- column sums -> 1/sum ----------------
__global__ __launch_bounds__(256) void colsum_k() {
    __shared__ float sh[256];
    const int b = blockIdx.y, i0 = blockIdx.x * 128;
    const int tid = threadIdx.x;
    const int i = i0 + (tid & 127), half = tid >> 7;
    const __nv_bfloat16* Pc = g_P + (size_t)b*T_*T_ + i;
    float s = 0.f;
    #pragma unroll 4
    for (int j = i0 + half; j < T_; j += 2)
        s += __bfloat162float(Pc[(size_t)j * T_]);
    sh[tid] = s;
    __syncthreads();
    if (tid < 128)
        g_crz[b*T_ + i0 + tid] = 1.0f / (sh[tid] + sh[tid + 128]);
}

// ---------------- scale Vt rows by crz (in place; Vt rewritten each run) -----
__global__ __launch_bounds__(256) void scalev_k() {
    int g = blockIdx.x * 256 + threadIdx.x;
    int o = g * 2;
    int b = o >> 20, i = o & (T_ - 1);
    __nv_bfloat162 v = ((__nv_bfloat162*)g_Vtb)[g];
    float2 f = __bfloat1622float2(v);
    f.x *= g_crz[b*T_ + i];
    f.y *= g_crz[b*T_ + i + 1];
    ((__nv_bfloat162*)g_Vtb)[g] = __floats2bfloat162_rn(f.x, f.y);
}

// ---------------- read = P @ Vs^T ----------------
__global__ __launch_bounds__(256) void read_t(float* __restrict__ out) {
    const int tid = threadIdx.x, wid = tid >> 5, lane = tid & 31;
    const int wm = (wid >> 2) * 64, wn = (wid & 3) * 32;
    const int b = blockIdx.z, m0 = blockIdx.y * 128, n0 = blockIdx.x * 128;
    const int nk = 4 * (blockIdx.y + 1);             // i <= j-tile max; P zero beyond
    const __nv_bfloat16* P = g_P   + (size_t)b*T_*T_ + (size_t)m0 * T_;
    const __nv_bfloat16* V = g_Vtb + (size_t)b*C_*T_ + (size_t)n0 * T_;

    float acc[4][4][4];
    gemm_pipe(acc, nk, tid, lane, wm, wn, [=](uint32_t ad, uint32_t bd, int k) {
        ldt32(ad, P + k*32, T_, tid);
        ldt32(bd, V + k*32, T_, tid);
    });

    const int gid = lane >> 2, tig = lane & 3;
    #pragma unroll
    for (int mt = 0; mt < 4; mt++)
        #pragma unroll
        for (int nt = 0; nt < 4; nt++)
            #pragma unroll
            for (int h = 0; h < 2; h++) {
                int m = m0 + wm + mt*16 + gid + h*8;
                int n = n0 + wn + nt*8 + tig*2;
                float* orow = out + ((size_t)b * T_ + m) * 1024 + 512;
                *(float2*)(orow + n) = make_float2(acc[mt][nt][h*2+0], acc[mt][nt][h*2+1]);
            }
}

// ---------------- copy input half ----------------
__global__ __launch_bounds__(256) void copy_k(const float* __restrict__ X, float* __restrict__ out) {
    int g = blockIdx.x * 256 + threadIdx.x;
    int row = g >> 7, c4 = g & 127;
    ((float4*)out)[(size_t)row * 256 + c4] = ((const float4*)X)[g];
}

// ---------------------------------------------------------------------------
extern "C" void kernel_launch(void* const* d_in, const int* in_sizes, int n_in,
                              void* d_out, int out_size)
{
    const float* X  = (const float*)d_in[0];
    const float* Wq = (const float*)d_in[1];
    const float* bq = (const float*)d_in[2];
    const float* Wk = (const float*)d_in[3];
    const float* bk = (const float*)d_in[4];
    const float* Wv = (const float*)d_in[5];
    const float* bv = (const float*)d_in[6];
    float* out = (float*)d_out;

    __nv_bfloat16* Xb; cudaGetSymbolAddress((void**)&Xb, g_Xb);
    __nv_bfloat16* Wb; cudaGetSymbolAddress((void**)&Wb, g_Wb);

    split_k<<<8192, 256>>>(X, Xb, BT_*C_/4);
    split_k<<<256, 256>>>(Wq, Wb,           C_*C_/4);
    split_k<<<256, 256>>>(Wk, Wb + C_*C_,   C_*C_/4);
    split_k<<<256, 256>>>(Wv, Wb + 2*C_*C_, C_*C_/4);
    qkv_t<<<dim3(4, 128, 3), 256>>>(bq, bk, bv);
    logits_t<<<dim3(136, 8), 256>>>();
    colsum_k<<<dim3(16, 8), 256>>>();
    scalev_k<<<16384, 256>>>();
    read_t<<<dim3(4, 16, 8), 256>>>(out);
    copy_k<<<8192, 256>>>(X, out);
}

// round 8
// speedup vs baseline: 4.1338x; 1.0523x over previous
#include <cuda_runtime.h>
#include <cuda_bf16.h>
#include <math.h>
#include <stdint.h>

#define B_ 8
#define T_ 2048
#define C_ 512
#define BT_ (B_*T_)
#define SCALE 0.044194173824159216f

// ---------------- globals ----------------
__device__ __nv_bfloat16 g_Xb[BT_*C_];
__device__ __nv_bfloat16 g_Wb[3*C_*C_];
__device__ __nv_bfloat16 g_Qb[BT_*C_];
__device__ __nv_bfloat16 g_Kb[BT_*C_];
__device__ __nv_bfloat16 g_Vtb[BT_*C_];          // [b][v][t], scaled in-place by crz
__device__ __nv_bfloat16 g_P[(size_t)B_*T_*T_];  // exp(S*scale) unnormalized; upper tiles stay 0
__device__ float g_crz[BT_];

// ---------------- helpers ----------------
__device__ __forceinline__ uint32_t smem_u32(const void* p) {
    uint32_t a;
    asm("{ .reg .u64 t; cvta.to.shared.u64 t, %1; cvt.u32.u64 %0, t; }" : "=r"(a) : "l"(p));
    return a;
}
__device__ __forceinline__ void cpa(uint32_t dst, const void* src) {
    asm volatile("cp.async.cg.shared.global [%0], [%1], 16;" :: "r"(dst), "l"(src));
}
__device__ __forceinline__ void ldsm4(uint32_t* r, uint32_t a) {
    asm volatile("ldmatrix.sync.aligned.m8n8.x4.shared.b16 {%0,%1,%2,%3}, [%4];"
        : "=r"(r[0]), "=r"(r[1]), "=r"(r[2]), "=r"(r[3]) : "r"(a));
}
__device__ __forceinline__ void ldsm2(uint32_t* r, uint32_t a) {
    asm volatile("ldmatrix.sync.aligned.m8n8.x2.shared.b16 {%0,%1}, [%2];"
        : "=r"(r[0]), "=r"(r[1]) : "r"(a));
}
__device__ __forceinline__ void mma16816(float* c, const uint32_t* a, const uint32_t* b) {
    asm volatile("mma.sync.aligned.m16n8k16.row.col.f32.bf16.bf16.f32 "
        "{%0,%1,%2,%3}, {%4,%5,%6,%7}, {%8,%9}, {%0,%1,%2,%3};"
        : "+f"(c[0]), "+f"(c[1]), "+f"(c[2]), "+f"(c[3])
        : "r"(a[0]), "r"(a[1]), "r"(a[2]), "r"(a[3]), "r"(b[0]), "r"(b[1]));
}

// smem tile: 128 rows x 32 bf16, row stride 40 elems (80B) -> conflict-free ldmatrix
#define RS 80                    // row stride bytes
#define MAT_BYTES (128*RS)       // 10240
#define STAGE_BYTES (2*MAT_BYTES)
#define NSTAGE 3
#define SMEM_TOT (NSTAGE*STAGE_BYTES)   // 61440

// load 128x32 bf16 tile gmem->smem via cp.async; src pre-offset (row0,k0); stride elems
__device__ __forceinline__ void ldt32(uint32_t dst, const __nv_bfloat16* src, int stride, int tid) {
    #pragma unroll
    for (int s = 0; s < 2; s++) {
        int slot = tid + s*256;
        int r = slot >> 2, c = slot & 3;
        cpa(dst + r*RS + c*16, (const char*)src + (size_t)r*stride*2 + c*16);
    }
}

// one BK=32 chunk of MMAs: warp tile 64(m)x32(n), acc[mt][nt][4]
__device__ __forceinline__ void compute_chunk(uint32_t aB, uint32_t bB, int lane,
                                              int wm, int wn, float acc[4][4][4]) {
    #pragma unroll
    for (int ks = 0; ks < 2; ks++) {
        uint32_t af[4][4], bf[4][2];
        int ar = wm + (lane & 15);
        int ak = ks*16 + ((lane >> 4) << 3);
        #pragma unroll
        for (int mt = 0; mt < 4; mt++) ldsm4(af[mt], aB + (ar + mt*16)*RS + ak*2);
        int br = wn + (lane & 7);
        int bk = ks*16 + (((lane >> 3) & 1) << 3);
        #pragma unroll
        for (int nt = 0; nt < 4; nt++) ldsm2(bf[nt], bB + (br + nt*8)*RS + bk*2);
        #pragma unroll
        for (int mt = 0; mt < 4; mt++)
            #pragma unroll
            for (int nt = 0; nt < 4; nt++)
                mma16816(acc[mt][nt], af[mt], bf[nt]);
    }
}

// 3-stage pipelined 128x128 GEMM; one __syncthreads per chunk
template<class F>
__device__ __forceinline__ void gemm_pipe(float acc[4][4][4], int nk, int tid,
                                          int lane, int wm, int wn, F load) {
    extern __shared__ __align__(16) char smbuf[];
    uint32_t sb = smem_u32(smbuf);
    #pragma unroll
    for (int mt = 0; mt < 4; mt++)
        #pragma unroll
        for (int nt = 0; nt < 4; nt++)
            #pragma unroll
            for (int c = 0; c < 4; c++) acc[mt][nt][c] = 0.f;

    #pragma unroll
    for (int s = 0; s < NSTAGE-1; s++) {      // nk >= 2 always
        uint32_t st = sb + s*STAGE_BYTES;
        load(st, st + MAT_BYTES, s);
        asm volatile("cp.async.commit_group;" ::: "memory");
    }
    int ldk = NSTAGE-1, lds = NSTAGE-1;       // next chunk to load, its stage
    int cs = 0;                               // stage being computed
    for (int k = 0; k < nk; k++) {
        asm volatile("cp.async.wait_group %0;" :: "n"(NSTAGE-2) : "memory");
        __syncthreads();
        if (ldk < nk) {
            uint32_t st = sb + lds*STAGE_BYTES;
            load(st, st + MAT_BYTES, ldk);
        }
        asm volatile("cp.async.commit_group;" ::: "memory");
        ldk++; if (++lds == NSTAGE) lds = 0;
        compute_chunk(sb + cs*STAGE_BYTES, sb + cs*STAGE_BYTES + MAT_BYTES, lane, wm, wn, acc);
        if (++cs == NSTAGE) cs = 0;
    }
}

// ---------------- fused: X fp32 -> (out left half, bf16 Xb) ----------------
__global__ __launch_bounds__(256) void xprep_k(const float* __restrict__ X,
                                               float* __restrict__ out,
                                               __nv_bfloat16* __restrict__ dst) {
    int g = blockIdx.x * 256 + threadIdx.x;     // 0 .. BT_*C_/4-1
    float4 v = ((const float4*)X)[g];
    int row = g >> 7, c4 = g & 127;
    ((float4*)out)[(size_t)row * 256 + c4] = v;
    __nv_bfloat162 a = __floats2bfloat162_rn(v.x, v.y);
    __nv_bfloat162 b = __floats2bfloat162_rn(v.z, v.w);
    uint2 o; o.x = *(uint32_t*)&a; o.y = *(uint32_t*)&b;
    ((uint2*)dst)[g] = o;
}

// ---------------- weights fp32 -> bf16 (z = which matrix) ----------------
__global__ __launch_bounds__(256) void wprep_k(const float* __restrict__ Wq,
                                               const float* __restrict__ Wk,
                                               const float* __restrict__ Wv,
                                               __nv_bfloat16* __restrict__ dst) {
    int z = blockIdx.y;
    const float* src = (z == 0) ? Wq : (z == 1) ? Wk : Wv;
    int g = blockIdx.x * 256 + threadIdx.x;     // 0 .. C_*C_/4-1
    float4 v = ((const float4*)src)[g];
    __nv_bfloat162 a = __floats2bfloat162_rn(v.x, v.y);
    __nv_bfloat162 b = __floats2bfloat162_rn(v.z, v.w);
    uint2 o; o.x = *(uint32_t*)&a; o.y = *(uint32_t*)&b;
    ((uint2*)(dst + (size_t)z * C_ * C_))[g] = o;
}

// ---------------- QKV projection ----------------
__global__ __launch_bounds__(256) void qkv_t(const float* __restrict__ bq,
                                             const float* __restrict__ bk,
                                             const float* __restrict__ bv) {
    const int tid = threadIdx.x, wid = tid >> 5, lane = tid & 31;
    const int wm = (wid >> 2) * 64, wn = (wid & 3) * 32;
    const int z = blockIdx.z, m0 = blockIdx.y * 128, n0 = blockIdx.x * 128;
    const __nv_bfloat16* A  = g_Xb + (size_t)m0 * C_;
    const __nv_bfloat16* Bm = g_Wb + (size_t)z * C_ * C_ + (size_t)n0 * C_;
    const float* bias = (z == 0) ? bq : (z == 1) ? bk : bv;

    float acc[4][4][4];
    gemm_pipe(acc, C_/32, tid, lane, wm, wn, [=](uint32_t ad, uint32_t bd, int k) {
        ldt32(ad, A  + k*32, C_, tid);
        ldt32(bd, Bm + k*32, C_, tid);
    });

    const int gid = lane >> 2, tig = lane & 3;
    #pragma unroll
    for (int mt = 0; mt < 4; mt++)
        #pragma unroll
        for (int nt = 0; nt < 4; nt++)
            #pragma unroll
            for (int h = 0; h < 2; h++) {
                int m = m0 + wm + mt*16 + gid + h*8;
                int n = n0 + wn + nt*8 + tig*2;
                float v0 = acc[mt][nt][h*2+0] + __ldg(bias + n);
                float v1 = acc[mt][nt][h*2+1] + __ldg(bias + n + 1);
                if (z < 2) {
                    __nv_bfloat16* Dst = (z == 0) ? g_Qb : g_Kb;
                    __nv_bfloat162 p = __floats2bfloat162_rn(v0, v1);
                    *(uint32_t*)(Dst + (size_t)m * C_ + n) = *(uint32_t*)&p;
                } else {
                    int bb = m >> 11, t = m & (T_ - 1);
                    g_Vtb[((size_t)bb * C_ + n)     * T_ + t] = __float2bfloat16_rn(v0);
                    g_Vtb[((size_t)bb * C_ + n + 1) * T_ + t] = __float2bfloat16_rn(v1);
                }
            }
}

// ---------------- logits -> unnormalized exp probs (bf16) ----------------
__global__ __launch_bounds__(256) void logits_t() {
    const int tid = threadIdx.x, wid = tid >> 5, lane = tid & 31;
    const int wm = (wid >> 2) * 64, wn = (wid & 3) * 32;
    const int b = blockIdx.y;
    int x = blockIdx.x;
    int jt = (int)((sqrtf(8.f*x + 1.f) - 1.f) * 0.5f);
    while ((jt + 1)*(jt + 2)/2 <= x) jt++;
    while (jt*(jt + 1)/2 > x) jt--;
    const int it = x - jt*(jt + 1)/2;
    const int m0 = jt * 128, n0 = it * 128;
    const __nv_bfloat16* Q = g_Qb + (size_t)b*T_*C_ + (size_t)m0 * C_;
    const __nv_bfloat16* K = g_Kb + (size_t)b*T_*C_ + (size_t)n0 * C_;

    float acc[4][4][4];
    gemm_pipe(acc, C_/32, tid, lane, wm, wn, [=](uint32_t ad, uint32_t bd, int k) {
        ldt32(ad, Q + k*32, C_, tid);
        ldt32(bd, K + k*32, C_, tid);
    });

    const int gid = lane >> 2, tig = lane & 3;
    __nv_bfloat16* Pb = g_P + (size_t)b*T_*T_;
    #pragma unroll
    for (int mt = 0; mt < 4; mt++)
        #pragma unroll
        for (int nt = 0; nt < 4; nt++)
            #pragma unroll
            for (int h = 0; h < 2; h++) {
                int j = m0 + wm + mt*16 + gid + h*8;
                int i = n0 + wn + nt*8 + tig*2;
                float e0 = (i+0 > j) ? 0.f : __expf(acc[mt][nt][h*2+0] * SCALE);
                float e1 = (i+1 > j) ? 0.f : __expf(acc[mt][nt][h*2+1] * SCALE);
                __nv_bfloat162 p = __floats2bfloat162_rn(e0, e1);
                *(uint32_t*)(Pb + (size_t)j * T_ + i) = *(uint32_t*)&p;
            }
}

// ---------------- column sums -> 1/sum ----------------
__global__ __launch_bounds__(256) void colsum_k() {
    __shared__ float sh[256];
    const int b = blockIdx.y, i0 = blockIdx.x * 128;
    const int tid = threadIdx.x;
    const int i = i0 + (tid & 127), half = tid >> 7;
    const __nv_bfloat16* Pc = g_P + (size_t)b*T_*T_ + i;
    float s = 0.f;
    #pragma unroll 4
    for (int j = i0 + half; j < T_; j += 2)
        s += __bfloat162float(Pc[(size_t)j * T_]);
    sh[tid] = s;
    __syncthreads();
    if (tid < 128)
        g_crz[b*T_ + i0 + tid] = 1.0f / (sh[tid] + sh[tid + 128]);
}

// ---------------- scale Vt rows by crz (in place; Vt rewritten each run) -----
__global__ __launch_bounds__(256) void scalev_k() {
    int g = blockIdx.x * 256 + threadIdx.x;
    int o = g * 2;
    int b = o >> 20, i = o & (T_ - 1);
    __nv_bfloat162 v = ((__nv_bfloat162*)g_Vtb)[g];
    float2 f = __bfloat1622float2(v);
    f.x *= g_crz[b*T_ + i];
    f.y *= g_crz[b*T_ + i + 1];
    ((__nv_bfloat162*)g_Vtb)[g] = __floats2bfloat162_rn(f.x, f.y);
}

// ---------------- read = P @ Vs^T ----------------
__global__ __launch_bounds__(256) void read_t(float* __restrict__ out) {
    const int tid = threadIdx.x, wid = tid >> 5, lane = tid & 31;
    const int wm = (wid >> 2) * 64, wn = (wid & 3) * 32;
    const int b = blockIdx.z, m0 = blockIdx.y * 128, n0 = blockIdx.x * 128;
    const int nk = 4 * (blockIdx.y + 1);             // i <= j-tile max; P zero beyond
    const __nv_bfloat16* P = g_P   + (size_t)b*T_*T_ + (size_t)m0 * T_;
    const __nv_bfloat16* V = g_Vtb + (size_t)b*C_*T_ + (size_t)n0 * T_;

    float acc[4][4][4];
    gemm_pipe(acc, nk, tid, lane, wm, wn, [=](uint32_t ad, uint32_t bd, int k) {
        ldt32(ad, P + k*32, T_, tid);
        ldt32(bd, V + k*32, T_, tid);
    });

    const int gid = lane >> 2, tig = lane & 3;
    #pragma unroll
    for (int mt = 0; mt < 4; mt++)
        #pragma unroll
        for (int nt = 0; nt < 4; nt++)
            #pragma unroll
            for (int h = 0; h < 2; h++) {
                int m = m0 + wm + mt*16 + gid + h*8;
                int n = n0 + wn + nt*8 + tig*2;
                float* orow = out + ((size_t)b * T_ + m) * 1024 + 512;
                *(float2*)(orow + n) = make_float2(acc[mt][nt][h*2+0], acc[mt][nt][h*2+1]);
            }
}

// ---------------------------------------------------------------------------
extern "C" void kernel_launch(void* const* d_in, const int* in_sizes, int n_in,
                              void* d_out, int out_size)
{
    const float* X  = (const float*)d_in[0];
    const float* Wq = (const float*)d_in[1];
    const float* bq = (const float*)d_in[2];
    const float* Wk = (const float*)d_in[3];
    const float* bk = (const float*)d_in[4];
    const float* Wv = (const float*)d_in[5];
    const float* bv = (const float*)d_in[6];
    float* out = (float*)d_out;

    cudaFuncSetAttribute(qkv_t,    cudaFuncAttributeMaxDynamicSharedMemorySize, SMEM_TOT);
    cudaFuncSetAttribute(logits_t, cudaFuncAttributeMaxDynamicSharedMemorySize, SMEM_TOT);
    cudaFuncSetAttribute(read_t,   cudaFuncAttributeMaxDynamicSharedMemorySize, SMEM_TOT);

    __nv_bfloat16* Xb; cudaGetSymbolAddress((void**)&Xb, g_Xb);
    __nv_bfloat16* Wb; cudaGetSymbolAddress((void**)&Wb, g_Wb);

    xprep_k<<<8192, 256>>>(X, out, Xb);
    wprep_k<<<dim3(256, 3), 256>>>(Wq, Wk, Wv, Wb);
    qkv_t<<<dim3(4, 128, 3), 256, SMEM_TOT>>>(bq, bk, bv);
    logits_t<<<dim3(136, 8), 256, SMEM_TOT>>>();
    colsum_k<<<dim3(16, 8), 256>>>();
    scalev_k<<<16384, 256>>>();
    read_t<<<dim3(4, 16, 8), 256, SMEM_TOT>>>(out);
}

// round 9
// speedup vs baseline: 4.5052x; 1.0899x over previous
#include <cuda_runtime.h>
#include <cuda_bf16.h>
#include <math.h>
#include <stdint.h>

#define B_ 8
#define T_ 2048
#define C_ 512
#define BT_ (B_*T_)
#define SCALE 0.044194173824159216f

// ---------------- globals ----------------
__device__ __nv_bfloat16 g_Xb[BT_*C_];
__device__ __nv_bfloat16 g_Wb[3*C_*C_];
__device__ __nv_bfloat16 g_Qb[BT_*C_];
__device__ __nv_bfloat16 g_Kb[BT_*C_];
__device__ __nv_bfloat16 g_Vtb[BT_*C_];          // [b][v][t], scaled in-place by crz
__device__ __nv_bfloat16 g_P[(size_t)B_*T_*T_];  // exp(S*scale) unnormalized; upper tiles stay 0
__device__ float g_crz[BT_];

// ---------------- helpers ----------------
__device__ __forceinline__ uint32_t smem_u32(const void* p) {
    uint32_t a;
    asm("{ .reg .u64 t; cvta.to.shared.u64 t, %1; cvt.u32.u64 %0, t; }" : "=r"(a) : "l"(p));
    return a;
}
__device__ __forceinline__ void cpa(uint32_t dst, const void* src) {
    asm volatile("cp.async.cg.shared.global [%0], [%1], 16;" :: "r"(dst), "l"(src));
}
__device__ __forceinline__ void ldsm4(uint32_t* r, uint32_t a) {
    asm volatile("ldmatrix.sync.aligned.m8n8.x4.shared.b16 {%0,%1,%2,%3}, [%4];"
        : "=r"(r[0]), "=r"(r[1]), "=r"(r[2]), "=r"(r[3]) : "r"(a));
}
__device__ __forceinline__ void mma16816(float* c, const uint32_t* a, const uint32_t* b) {
    asm volatile("mma.sync.aligned.m16n8k16.row.col.f32.bf16.bf16.f32 "
        "{%0,%1,%2,%3}, {%4,%5,%6,%7}, {%8,%9}, {%0,%1,%2,%3};"
        : "+f"(c[0]), "+f"(c[1]), "+f"(c[2]), "+f"(c[3])
        : "r"(a[0]), "r"(a[1]), "r"(a[2]), "r"(a[3]), "r"(b[0]), "r"(b[1]));
}

// smem tile: 128 rows x 64 bf16, row stride 144B (128B data + 16B pad -> conflict-free ldmatrix)
#define RS 144
#define MAT_BYTES (128*RS)        // 18432
#define STAGE_BYTES (2*MAT_BYTES) // 36864
#define NSTAGE 3
#define SMEM_TOT (NSTAGE*STAGE_BYTES)   // 110592

// load 128x64 bf16 tile gmem->smem via cp.async; src pre-offset (row0,k0); stride elems
__device__ __forceinline__ void ldt64(uint32_t dst, const __nv_bfloat16* src, int stride, int tid) {
    #pragma unroll
    for (int s = 0; s < 4; s++) {
        int slot = tid + s*256;
        int r = slot >> 3, c = slot & 7;
        cpa(dst + r*RS + c*16, (const char*)src + (size_t)r*stride*2 + c*16);
    }
}

// load register fragments for one ks (K=16 slice) of a BK=64 chunk
__device__ __forceinline__ void load_frags(uint32_t aB, uint32_t bB, int ks, int lane,
                                           int wm, int wn, uint32_t af[4][4], uint32_t bf[4][2]) {
    int ar = wm + (lane & 15);
    int ak = ks*16 + ((lane >> 4) << 3);
    #pragma unroll
    for (int mt = 0; mt < 4; mt++) ldsm4(af[mt], aB + (ar + mt*16)*RS + ak*2);
    // B: one ldsm4 = two n8k16 fragments
    int brow = (lane & 7) + ((lane >> 4) & 1) * 8;
    int bk = ks*16 + (((lane >> 3) & 1) << 3);
    #pragma unroll
    for (int ng = 0; ng < 2; ng++) {
        uint32_t r[4];
        ldsm4(r, bB + (wn + ng*16 + brow)*RS + bk*2);
        bf[ng*2+0][0] = r[0]; bf[ng*2+0][1] = r[1];
        bf[ng*2+1][0] = r[2]; bf[ng*2+1][1] = r[3];
    }
}

// one BK=64 chunk: 4 ks steps, register double-buffered fragments
__device__ __forceinline__ void compute_chunk(uint32_t aB, uint32_t bB, int lane,
                                              int wm, int wn, float acc[4][4][4]) {
    uint32_t af[2][4][4], bf[2][4][2];
    load_frags(aB, bB, 0, lane, wm, wn, af[0], bf[0]);
    #pragma unroll
    for (int ks = 0; ks < 4; ks++) {
        int cur = ks & 1;
        if (ks < 3) load_frags(aB, bB, ks + 1, lane, wm, wn, af[cur^1], bf[cur^1]);
        #pragma unroll
        for (int mt = 0; mt < 4; mt++)
            #pragma unroll
            for (int nt = 0; nt < 4; nt++)
                mma16816(acc[mt][nt], af[cur][mt], bf[cur][nt]);
    }
}

// 3-stage pipelined GEMM over BK=64 chunks; one __syncthreads per chunk
template<class F>
__device__ __forceinline__ void gemm_pipe(float acc[4][4][4], int nk, int tid,
                                          int lane, int wm, int wn, F load) {
    extern __shared__ __align__(16) char smbuf[];
    uint32_t sb = smem_u32(smbuf);
    #pragma unroll
    for (int mt = 0; mt < 4; mt++)
        #pragma unroll
        for (int nt = 0; nt < 4; nt++)
            #pragma unroll
            for (int c = 0; c < 4; c++) acc[mt][nt][c] = 0.f;

    #pragma unroll
    for (int s = 0; s < NSTAGE-1; s++) {      // nk >= 2 always
        uint32_t st = sb + s*STAGE_BYTES;
        load(st, st + MAT_BYTES, s);
        asm volatile("cp.async.commit_group;" ::: "memory");
    }
    int ldk = NSTAGE-1, lds = NSTAGE-1;
    int cs = 0;
    for (int k = 0; k < nk; k++) {
        asm volatile("cp.async.wait_group %0;" :: "n"(NSTAGE-2) : "memory");
        __syncthreads();
        if (ldk < nk) {
            uint32_t st = sb + lds*STAGE_BYTES;
            load(st, st + MAT_BYTES, ldk);
        }
        asm volatile("cp.async.commit_group;" ::: "memory");
        ldk++; if (++lds == NSTAGE) lds = 0;
        compute_chunk(sb + cs*STAGE_BYTES, sb + cs*STAGE_BYTES + MAT_BYTES, lane, wm, wn, acc);
        if (++cs == NSTAGE) cs = 0;
    }
}

// ---------------- fused: X fp32 -> (out left half, bf16 Xb) ----------------
__global__ __launch_bounds__(256) void xprep_k(const float* __restrict__ X,
                                               float* __restrict__ out,
                                               __nv_bfloat16* __restrict__ dst) {
    int g = blockIdx.x * 256 + threadIdx.x;
    float4 v = ((const float4*)X)[g];
    int row = g >> 7, c4 = g & 127;
    ((float4*)out)[(size_t)row * 256 + c4] = v;
    __nv_bfloat162 a = __floats2bfloat162_rn(v.x, v.y);
    __nv_bfloat162 b = __floats2bfloat162_rn(v.z, v.w);
    uint2 o; o.x = *(uint32_t*)&a; o.y = *(uint32_t*)&b;
    ((uint2*)dst)[g] = o;
}

// ---------------- weights fp32 -> bf16 ----------------
__global__ __launch_bounds__(256) void wprep_k(const float* __restrict__ Wq,
                                               const float* __restrict__ Wk,
                                               const float* __restrict__ Wv,
                                               __nv_bfloat16* __restrict__ dst) {
    int z = blockIdx.y;
    const float* src = (z == 0) ? Wq : (z == 1) ? Wk : Wv;
    int g = blockIdx.x * 256 + threadIdx.x;
    float4 v = ((const float4*)src)[g];
    __nv_bfloat162 a = __floats2bfloat162_rn(v.x, v.y);
    __nv_bfloat162 b = __floats2bfloat162_rn(v.z, v.w);
    uint2 o; o.x = *(uint32_t*)&a; o.y = *(uint32_t*)&b;
    ((uint2*)(dst + (size_t)z * C_ * C_))[g] = o;
}

// ---------------- QKV projection ----------------
__global__ __launch_bounds__(256) void qkv_t(const float* __restrict__ bq,
                                             const float* __restrict__ bk,
                                             const float* __restrict__ bv) {
    const int tid = threadIdx.x, wid = tid >> 5, lane = tid & 31;
    const int wm = (wid >> 2) * 64, wn = (wid & 3) * 32;
    const int z = blockIdx.z, m0 = blockIdx.y * 128, n0 = blockIdx.x * 128;
    const __nv_bfloat16* A  = g_Xb + (size_t)m0 * C_;
    const __nv_bfloat16* Bm = g_Wb + (size_t)z * C_ * C_ + (size_t)n0 * C_;
    const float* bias = (z == 0) ? bq : (z == 1) ? bk : bv;

    float acc[4][4][4];
    gemm_pipe(acc, C_/64, tid, lane, wm, wn, [=](uint32_t ad, uint32_t bd, int k) {
        ldt64(ad, A  + k*64, C_, tid);
        ldt64(bd, Bm + k*64, C_, tid);
    });

    const int gid = lane >> 2, tig = lane & 3;
    #pragma unroll
    for (int mt = 0; mt < 4; mt++)
        #pragma unroll
        for (int nt = 0; nt < 4; nt++)
            #pragma unroll
            for (int h = 0; h < 2; h++) {
                int m = m0 + wm + mt*16 + gid + h*8;
                int n = n0 + wn + nt*8 + tig*2;
                float v0 = acc[mt][nt][h*2+0] + __ldg(bias + n);
                float v1 = acc[mt][nt][h*2+1] + __ldg(bias + n + 1);
                if (z < 2) {
                    __nv_bfloat16* Dst = (z == 0) ? g_Qb : g_Kb;
                    __nv_bfloat162 p = __floats2bfloat162_rn(v0, v1);
                    *(uint32_t*)(Dst + (size_t)m * C_ + n) = *(uint32_t*)&p;
                } else {
                    int bb = m >> 11, t = m & (T_ - 1);
                    g_Vtb[((size_t)bb * C_ + n)     * T_ + t] = __float2bfloat16_rn(v0);
                    g_Vtb[((size_t)bb * C_ + n + 1) * T_ + t] = __float2bfloat16_rn(v1);
                }
            }
}

// ---------------- logits -> unnormalized exp probs (bf16) ----------------
__global__ __launch_bounds__(256) void logits_t() {
    const int tid = threadIdx.x, wid = tid >> 5, lane = tid & 31;
    const int wm = (wid >> 2) * 64, wn = (wid & 3) * 32;
    const int b = blockIdx.y;
    int x = blockIdx.x;
    int jt = (int)((sqrtf(8.f*x + 1.f) - 1.f) * 0.5f);
    while ((jt + 1)*(jt + 2)/2 <= x) jt++;
    while (jt*(jt + 1)/2 > x) jt--;
    const int it = x - jt*(jt + 1)/2;
    const int m0 = jt * 128, n0 = it * 128;
    const __nv_bfloat16* Q = g_Qb + (size_t)b*T_*C_ + (size_t)m0 * C_;
    const __nv_bfloat16* K = g_Kb + (size_t)b*T_*C_ + (size_t)n0 * C_;

    float acc[4][4][4];
    gemm_pipe(acc, C_/64, tid, lane, wm, wn, [=](uint32_t ad, uint32_t bd, int k) {
        ldt64(ad, Q + k*64, C_, tid);
        ldt64(bd, K + k*64, C_, tid);
    });

    const int gid = lane >> 2, tig = lane & 3;
    __nv_bfloat16* Pb = g_P + (size_t)b*T_*T_;
    #pragma unroll
    for (int mt = 0; mt < 4; mt++)
        #pragma unroll
        for (int nt = 0; nt < 4; nt++)
            #pragma unroll
            for (int h = 0; h < 2; h++) {
                int j = m0 + wm + mt*16 + gid + h*8;
                int i = n0 + wn + nt*8 + tig*2;
                float e0 = (i+0 > j) ? 0.f : __expf(acc[mt][nt][h*2+0] * SCALE);
                float e1 = (i+1 > j) ? 0.f : __expf(acc[mt][nt][h*2+1] * SCALE);
                __nv_bfloat162 p = __floats2bfloat162_rn(e0, e1);
                *(uint32_t*)(Pb + (size_t)j * T_ + i) = *(uint32_t*)&p;
            }
}

// ---------------- column sums -> 1/sum ----------------
__global__ __launch_bounds__(256) void colsum_k() {
    __shared__ float sh[256];
    const int b = blockIdx.y, i0 = blockIdx.x * 128;
    const int tid = threadIdx.x;
    const int i = i0 + (tid & 127), half = tid >> 7;
    const __nv_bfloat16* Pc = g_P + (size_t)b*T_*T_ + i;
    float s = 0.f;
    #pragma unroll 4
    for (int j = i0 + half; j < T_; j += 2)
        s += __bfloat162float(Pc[(size_t)j * T_]);
    sh[tid] = s;
    __syncthreads();
    if (tid < 128)
        g_crz[b*T_ + i0 + tid] = 1.0f / (sh[tid] + sh[tid + 128]);
}

// ---------------- scale Vt rows by crz ----------------
__global__ __launch_bounds__(256) void scalev_k() {
    int g = blockIdx.x * 256 + threadIdx.x;
    int o = g * 2;
    int b = o >> 20, i = o & (T_ - 1);
    __nv_bfloat162 v = ((__nv_bfloat162*)g_Vtb)[g];
    float2 f = __bfloat1622float2(v);
    f.x *= g_crz[b*T_ + i];
    f.y *= g_crz[b*T_ + i + 1];
    ((__nv_bfloat162*)g_Vtb)[g] = __floats2bfloat162_rn(f.x, f.y);
}

// ---------------- read = P @ Vs^T ----------------
__global__ __launch_bounds__(256) void read_t(float* __restrict__ out) {
    const int tid = threadIdx.x, wid = tid >> 5, lane = tid & 31;
    const int wm = (wid >> 2) * 64, wn = (wid & 3) * 32;
    const int b = blockIdx.z, m0 = blockIdx.y * 128, n0 = blockIdx.x * 128;
    const int nk = 2 * (blockIdx.y + 1);             // BK=64 chunks; P zero beyond diag
    const __nv_bfloat16* P = g_P   + (size_t)b*T_*T_ + (size_t)m0 * T_;
    const __nv_bfloat16* V = g_Vtb + (size_t)b*C_*T_ + (size_t)n0 * T_;

    float acc[4][4][4];
    gemm_pipe(acc, nk, tid, lane, wm, wn, [=](uint32_t ad, uint32_t bd, int k) {
        ldt64(ad, P + k*64, T_, tid);
        ldt64(bd, V + k*64, T_, tid);
    });

    const int gid = lane >> 2, tig = lane & 3;
    #pragma unroll
    for (int mt = 0; mt < 4; mt++)
        #pragma unroll
        for (int nt = 0; nt < 4; nt++)
            #pragma unroll
            for (int h = 0; h < 2; h++) {
                int m = m0 + wm + mt*16 + gid + h*8;
                int n = n0 + wn + nt*8 + tig*2;
                float* orow = out + ((size_t)b * T_ + m) * 1024 + 512;
                *(float2*)(orow + n) = make_float2(acc[mt][nt][h*2+0], acc[mt][nt][h*2+1]);
            }
}

// ---------------------------------------------------------------------------
extern "C" void kernel_launch(void* const* d_in, const int* in_sizes, int n_in,
                              void* d_out, int out_size)
{
    const float* X  = (const float*)d_in[0];
    const float* Wq = (const float*)d_in[1];
    const float* bq = (const float*)d_in[2];
    const float* Wk = (const float*)d_in[3];
    const float* bk = (const float*)d_in[4];
    const float* Wv = (const float*)d_in[5];
    const float* bv = (const float*)d_in[6];
    float* out = (float*)d_out;

    cudaFuncSetAttribute(qkv_t,    cudaFuncAttributeMaxDynamicSharedMemorySize, SMEM_TOT);
    cudaFuncSetAttribute(logits_t, cudaFuncAttributeMaxDynamicSharedMemorySize, SMEM_TOT);
    cudaFuncSetAttribute(read_t,   cudaFuncAttributeMaxDynamicSharedMemorySize, SMEM_TOT);

    __nv_bfloat16* Xb; cudaGetSymbolAddress((void**)&Xb, g_Xb);
    __nv_bfloat16* Wb; cudaGetSymbolAddress((void**)&Wb, g_Wb);

    xprep_k<<<8192, 256>>>(X, out, Xb);
    wprep_k<<<dim3(256, 3), 256>>>(Wq, Wk, Wv, Wb);
    qkv_t<<<dim3(4, 128, 3), 256, SMEM_TOT>>>(bq, bk, bv);
    logits_t<<<dim3(136, 8), 256, SMEM_TOT>>>();
    colsum_k<<<dim3(16, 8), 256>>>();
    scalev_k<<<16384, 256>>>();
    read_t<<<dim3(4, 16, 8), 256, SMEM_TOT>>>(out);
}

// round 10
// speedup vs baseline: 5.8525x; 1.2990x over previous
#include <cuda_runtime.h>
#include <cuda_bf16.h>
#include <math.h>
#include <stdint.h>

#define B_ 8
#define T_ 2048
#define C_ 512
#define BT_ (B_*T_)
#define SCALE 0.044194173824159216f

// ---------------- globals ----------------
__device__ __nv_bfloat16 g_Xb[BT_*C_];
__device__ __nv_bfloat16 g_Wb[3*C_*C_];
__device__ __nv_bfloat16 g_Qb[BT_*C_];
__device__ __nv_bfloat16 g_Kb[BT_*C_];
__device__ __nv_bfloat16 g_Vtb[BT_*C_];          // [b][v][t], scaled in-place by 1/colsum
__device__ __nv_bfloat16 g_P[(size_t)B_*T_*T_];  // exp(S*scale) unnormalized; upper tiles stay 0
__device__ float g_csum[BT_];                    // per-(b,i) column sums (atomic)

// ---------------- helpers ----------------
__device__ __forceinline__ uint32_t smem_u32(const void* p) {
    uint32_t a;
    asm("{ .reg .u64 t; cvta.to.shared.u64 t, %1; cvt.u32.u64 %0, t; }" : "=r"(a) : "l"(p));
    return a;
}
__device__ __forceinline__ void cpa(uint32_t dst, const void* src) {
    asm volatile("cp.async.cg.shared.global [%0], [%1], 16;" :: "r"(dst), "l"(src));
}
__device__ __forceinline__ void ldsm4(uint32_t* r, uint32_t a) {
    asm volatile("ldmatrix.sync.aligned.m8n8.x4.shared.b16 {%0,%1,%2,%3}, [%4];"
        : "=r"(r[0]), "=r"(r[1]), "=r"(r[2]), "=r"(r[3]) : "r"(a));
}
__device__ __forceinline__ void mma16816(float* c, const uint32_t* a, const uint32_t* b) {
    asm volatile("mma.sync.aligned.m16n8k16.row.col.f32.bf16.bf16.f32 "
        "{%0,%1,%2,%3}, {%4,%5,%6,%7}, {%8,%9}, {%0,%1,%2,%3};"
        : "+f"(c[0]), "+f"(c[1]), "+f"(c[2]), "+f"(c[3])
        : "r"(a[0]), "r"(a[1]), "r"(a[2]), "r"(a[3]), "r"(b[0]), "r"(b[1]));
}

// smem tile: 128 rows x 64 bf16, row stride 144B (128B data + 16B pad -> conflict-free ldmatrix)
#define RS 144
#define MAT_BYTES (128*RS)        // 18432
#define STAGE_BYTES (2*MAT_BYTES) // 36864
#define NSTAGE 3
#define SMEM_TOT (NSTAGE*STAGE_BYTES)   // 110592

// load 128x64 bf16 tile gmem->smem via cp.async; src pre-offset (row0,k0); stride elems
__device__ __forceinline__ void ldt64(uint32_t dst, const __nv_bfloat16* src, int stride, int tid) {
    #pragma unroll
    for (int s = 0; s < 4; s++) {
        int slot = tid + s*256;
        int r = slot >> 3, c = slot & 7;
        cpa(dst + r*RS + c*16, (const char*)src + (size_t)r*stride*2 + c*16);
    }
}

// load register fragments for one ks (K=16 slice) of a BK=64 chunk
__device__ __forceinline__ void load_frags(uint32_t aB, uint32_t bB, int ks, int lane,
                                           int wm, int wn, uint32_t af[4][4], uint32_t bf[4][2]) {
    int ar = wm + (lane & 15);
    int ak = ks*16 + ((lane >> 4) << 3);
    #pragma unroll
    for (int mt = 0; mt < 4; mt++) ldsm4(af[mt], aB + (ar + mt*16)*RS + ak*2);
    int brow = (lane & 7) + ((lane >> 4) & 1) * 8;
    int bk = ks*16 + (((lane >> 3) & 1) << 3);
    #pragma unroll
    for (int ng = 0; ng < 2; ng++) {
        uint32_t r[4];
        ldsm4(r, bB + (wn + ng*16 + brow)*RS + bk*2);
        bf[ng*2+0][0] = r[0]; bf[ng*2+0][1] = r[1];
        bf[ng*2+1][0] = r[2]; bf[ng*2+1][1] = r[3];
    }
}

// one BK=64 chunk: 4 ks steps, register double-buffered fragments
__device__ __forceinline__ void compute_chunk(uint32_t aB, uint32_t bB, int lane,
                                              int wm, int wn, float acc[4][4][4]) {
    uint32_t af[2][4][4], bf[2][4][2];
    load_frags(aB, bB, 0, lane, wm, wn, af[0], bf[0]);
    #pragma unroll
    for (int ks = 0; ks < 4; ks++) {
        int cur = ks & 1;
        if (ks < 3) load_frags(aB, bB, ks + 1, lane, wm, wn, af[cur^1], bf[cur^1]);
        #pragma unroll
        for (int mt = 0; mt < 4; mt++)
            #pragma unroll
            for (int nt = 0; nt < 4; nt++)
                mma16816(acc[mt][nt], af[cur][mt], bf[cur][nt]);
    }
}

// 3-stage pipelined GEMM over BK=64 chunks; one __syncthreads per chunk
template<class F>
__device__ __forceinline__ void gemm_pipe(float acc[4][4][4], int nk, int tid,
                                          int lane, int wm, int wn, F load) {
    extern __shared__ __align__(16) char smbuf[];
    uint32_t sb = smem_u32(smbuf);
    #pragma unroll
    for (int mt = 0; mt < 4; mt++)
        #pragma unroll
        for (int nt = 0; nt < 4; nt++)
            #pragma unroll
            for (int c = 0; c < 4; c++) acc[mt][nt][c] = 0.f;

    #pragma unroll
    for (int s = 0; s < NSTAGE-1; s++) {
        uint32_t st = sb + s*STAGE_BYTES;
        load(st, st + MAT_BYTES, s);
        asm volatile("cp.async.commit_group;" ::: "memory");
    }
    int ldk = NSTAGE-1, lds = NSTAGE-1;
    int cs = 0;
    for (int k = 0; k < nk; k++) {
        asm volatile("cp.async.wait_group %0;" :: "n"(NSTAGE-2) : "memory");
        __syncthreads();
        if (ldk < nk) {
            uint32_t st = sb + lds*STAGE_BYTES;
            load(st, st + MAT_BYTES, ldk);
        }
        asm volatile("cp.async.commit_group;" ::: "memory");
        ldk++; if (++lds == NSTAGE) lds = 0;
        compute_chunk(sb + cs*STAGE_BYTES, sb + cs*STAGE_BYTES + MAT_BYTES, lane, wm, wn, acc);
        if (++cs == NSTAGE) cs = 0;
    }
}

// ---------------- fused: X fp32 -> (out left half, bf16 Xb); first blocks zero csum ----
__global__ __launch_bounds__(256) void xprep_k(const float* __restrict__ X,
                                               float* __restrict__ out,
                                               __nv_bfloat16* __restrict__ dst) {
    if (blockIdx.x < 16)
        ((float4*)g_csum)[blockIdx.x * 256 + threadIdx.x] = make_float4(0.f, 0.f, 0.f, 0.f);
    int g = blockIdx.x * 256 + threadIdx.x;
    float4 v = ((const float4*)X)[g];
    int row = g >> 7, c4 = g & 127;
    ((float4*)out)[(size_t)row * 256 + c4] = v;
    __nv_bfloat162 a = __floats2bfloat162_rn(v.x, v.y);
    __nv_bfloat162 b = __floats2bfloat162_rn(v.z, v.w);
    uint2 o; o.x = *(uint32_t*)&a; o.y = *(uint32_t*)&b;
    ((uint2*)dst)[g] = o;
}

// ---------------- weights fp32 -> bf16 ----------------
__global__ __launch_bounds__(256) void wprep_k(const float* __restrict__ Wq,
                                               const float* __restrict__ Wk,
                                               const float* __restrict__ Wv,
                                               __nv_bfloat16* __restrict__ dst) {
    int z = blockIdx.y;
    const float* src = (z == 0) ? Wq : (z == 1) ? Wk : Wv;
    int g = blockIdx.x * 256 + threadIdx.x;
    float4 v = ((const float4*)src)[g];
    __nv_bfloat162 a = __floats2bfloat162_rn(v.x, v.y);
    __nv_bfloat162 b = __floats2bfloat162_rn(v.z, v.w);
    uint2 o; o.x = *(uint32_t*)&a; o.y = *(uint32_t*)&b;
    ((uint2*)(dst + (size_t)z * C_ * C_))[g] = o;
}

// ---------------- QKV projection ----------------
__global__ __launch_bounds__(256) void qkv_t(const float* __restrict__ bq,
                                             const float* __restrict__ bk,
                                             const float* __restrict__ bv) {
    const int tid = threadIdx.x, wid = tid >> 5, lane = tid & 31;
    const int wm = (wid >> 2) * 64, wn = (wid & 3) * 32;
    const int z = blockIdx.z, m0 = blockIdx.y * 128, n0 = blockIdx.x * 128;
    const __nv_bfloat16* A  = g_Xb + (size_t)m0 * C_;
    const __nv_bfloat16* Bm = g_Wb + (size_t)z * C_ * C_ + (size_t)n0 * C_;
    const float* bias = (z == 0) ? bq : (z == 1) ? bk : bv;

    float acc[4][4][4];
    gemm_pipe(acc, C_/64, tid, lane, wm, wn, [=](uint32_t ad, uint32_t bd, int k) {
        ldt64(ad, A  + k*64, C_, tid);
        ldt64(bd, Bm + k*64, C_, tid);
    });

    const int gid = lane >> 2, tig = lane & 3;
    #pragma unroll
    for (int mt = 0; mt < 4; mt++)
        #pragma unroll
        for (int nt = 0; nt < 4; nt++)
            #pragma unroll
            for (int h = 0; h < 2; h++) {
                int m = m0 + wm + mt*16 + gid + h*8;
                int n = n0 + wn + nt*8 + tig*2;
                float v0 = acc[mt][nt][h*2+0] + __ldg(bias + n);
                float v1 = acc[mt][nt][h*2+1] + __ldg(bias + n + 1);
                if (z < 2) {
                    __nv_bfloat16* Dst = (z == 0) ? g_Qb : g_Kb;
                    __nv_bfloat162 p = __floats2bfloat162_rn(v0, v1);
                    *(uint32_t*)(Dst + (size_t)m * C_ + n) = *(uint32_t*)&p;
                } else {
                    int bb = m >> 11, t = m & (T_ - 1);
                    g_Vtb[((size_t)bb * C_ + n)     * T_ + t] = __float2bfloat16_rn(v0);
                    g_Vtb[((size_t)bb * C_ + n + 1) * T_ + t] = __float2bfloat16_rn(v1);
                }
            }
}

// ---------------- logits -> unnormalized exp probs (bf16) + fused column sums ----
__global__ __launch_bounds__(256) void logits_t() {
    const int tid = threadIdx.x, wid = tid >> 5, lane = tid & 31;
    const int wm = (wid >> 2) * 64, wn = (wid & 3) * 32;
    const int b = blockIdx.y;
    int x = blockIdx.x;
    int jt = (int)((sqrtf(8.f*x + 1.f) - 1.f) * 0.5f);
    while ((jt + 1)*(jt + 2)/2 <= x) jt++;
    while (jt*(jt + 1)/2 > x) jt--;
    const int it = x - jt*(jt + 1)/2;
    const int m0 = jt * 128, n0 = it * 128;
    const __nv_bfloat16* Q = g_Qb + (size_t)b*T_*C_ + (size_t)m0 * C_;
    const __nv_bfloat16* K = g_Kb + (size_t)b*T_*C_ + (size_t)n0 * C_;

    float acc[4][4][4];
    gemm_pipe(acc, C_/64, tid, lane, wm, wn, [=](uint32_t ad, uint32_t bd, int k) {
        ldt64(ad, Q + k*64, C_, tid);
        ldt64(bd, K + k*64, C_, tid);
    });

    const int gid = lane >> 2, tig = lane & 3;
    __nv_bfloat16* Pb = g_P + (size_t)b*T_*T_;
    float cs[4][2];
    #pragma unroll
    for (int nt = 0; nt < 4; nt++) { cs[nt][0] = 0.f; cs[nt][1] = 0.f; }

    #pragma unroll
    for (int mt = 0; mt < 4; mt++)
        #pragma unroll
        for (int nt = 0; nt < 4; nt++)
            #pragma unroll
            for (int h = 0; h < 2; h++) {
                int j = m0 + wm + mt*16 + gid + h*8;
                int i = n0 + wn + nt*8 + tig*2;
                float e0 = (i+0 > j) ? 0.f : __expf(acc[mt][nt][h*2+0] * SCALE);
                float e1 = (i+1 > j) ? 0.f : __expf(acc[mt][nt][h*2+1] * SCALE);
                __nv_bfloat162 p = __floats2bfloat162_rn(e0, e1);
                *(uint32_t*)(Pb + (size_t)j * T_ + i) = *(uint32_t*)&p;
                // accumulate the ROUNDED values so denominator matches stored numerators
                cs[nt][0] += __low2float(p);
                cs[nt][1] += __high2float(p);
            }

    // reduce over gid (lanes 4 apart), lanes 0-3 hold totals; atomic into g_csum
    #pragma unroll
    for (int nt = 0; nt < 4; nt++)
        #pragma unroll
        for (int c = 0; c < 2; c++) {
            float s = cs[nt][c];
            s += __shfl_down_sync(0xffffffffu, s, 16);
            s += __shfl_down_sync(0xffffffffu, s, 8);
            s += __shfl_down_sync(0xffffffffu, s, 4);
            if (gid == 0)
                atomicAdd(&g_csum[b*T_ + n0 + wn + nt*8 + tig*2 + c], s);
        }
}

// ---------------- scale Vt rows by 1/colsum ----------------
__global__ __launch_bounds__(256) void scalev_k() {
    int g = blockIdx.x * 256 + threadIdx.x;
    int o = g * 2;
    int b = o >> 20, i = o & (T_ - 1);
    __nv_bfloat162 v = ((__nv_bfloat162*)g_Vtb)[g];
    float2 f = __bfloat1622float2(v);
    f.x *= 1.0f / g_csum[b*T_ + i];
    f.y *= 1.0f / g_csum[b*T_ + i + 1];
    ((__nv_bfloat162*)g_Vtb)[g] = __floats2bfloat162_rn(f.x, f.y);
}

// ---------------- read = P @ Vs^T (longest-first scheduling) ----------------
__global__ __launch_bounds__(256) void read_t(float* __restrict__ out) {
    const int tid = threadIdx.x, wid = tid >> 5, lane = tid & 31;
    const int wm = (wid >> 2) * 64, wn = (wid & 3) * 32;
    const int b = blockIdx.z;
    const int jt = 15 - blockIdx.y;                  // longest CTAs dispatch first
    const int m0 = jt * 128, n0 = blockIdx.x * 128;
    const int nk = 2 * (jt + 1);                     // BK=64 chunks; P zero beyond diag
    const __nv_bfloat16* P = g_P   + (size_t)b*T_*T_ + (size_t)m0 * T_;
    const __nv_bfloat16* V = g_Vtb + (size_t)b*C_*T_ + (size_t)n0 * T_;

    float acc[4][4][4];
    gemm_pipe(acc, nk, tid, lane, wm, wn, [=](uint32_t ad, uint32_t bd, int k) {
        ldt64(ad, P + k*64, T_, tid);
        ldt64(bd, V + k*64, T_, tid);
    });

    const int gid = lane >> 2, tig = lane & 3;
    #pragma unroll
    for (int mt = 0; mt < 4; mt++)
        #pragma unroll
        for (int nt = 0; nt < 4; nt++)
            #pragma unroll
            for (int h = 0; h < 2; h++) {
                int m = m0 + wm + mt*16 + gid + h*8;
                int n = n0 + wn + nt*8 + tig*2;
                float* orow = out + ((size_t)b * T_ + m) * 1024 + 512;
                *(float2*)(orow + n) = make_float2(acc[mt][nt][h*2+0], acc[mt][nt][h*2+1]);
            }
}

// ---------------------------------------------------------------------------
extern "C" void kernel_launch(void* const* d_in, const int* in_sizes, int n_in,
                              void* d_out, int out_size)
{
    const float* X  = (const float*)d_in[0];
    const float* Wq = (const float*)d_in[1];
    const float* bq = (const float*)d_in[2];
    const float* Wk = (const float*)d_in[3];
    const float* bk = (const float*)d_in[4];
    const float* Wv = (const float*)d_in[5];
    const float* bv = (const float*)d_in[6];
    float* out = (float*)d_out;

    cudaFuncSetAttribute(qkv_t,    cudaFuncAttributeMaxDynamicSharedMemorySize, SMEM_TOT);
    cudaFuncSetAttribute(logits_t, cudaFuncAttributeMaxDynamicSharedMemorySize, SMEM_TOT);
    cudaFuncSetAttribute(read_t,   cudaFuncAttributeMaxDynamicSharedMemorySize, SMEM_TOT);

    __nv_bfloat16* Xb; cudaGetSymbolAddress((void**)&Xb, g_Xb);
    __nv_bfloat16* Wb; cudaGetSymbolAddress((void**)&Wb, g_Wb);

    xprep_k<<<8192, 256>>>(X, out, Xb);
    wprep_k<<<dim3(256, 3), 256>>>(Wq, Wk, Wv, Wb);
    qkv_t<<<dim3(4, 128, 3), 256, SMEM_TOT>>>(bq, bk, bv);
    logits_t<<<dim3(136, 8), 256, SMEM_TOT>>>();
    scalev_k<<<16384, 256>>>();
    read_t<<<dim3(4, 16, 8), 256, SMEM_TOT>>>(out);
}